// round 12
// baseline (speedup 1.0000x reference)
#include <cuda_runtime.h>
#include <cuda_fp16.h>
#include <cstdint>

// ---------------- problem constants ----------------
#define D_DIM   256      // embedding dim = GEMM K
#define NHID    512      // H*K_hid = GEMM N
#define TM      128      // nodes per CTA (4 warps x m32)
#define T1      128      // threads in score kernel (4 warps)
#define N_MAX   200704

// g_B4: W1 transposed, fp16, mma-fragment packed with CONTIGUOUS-k permutation.
// uint4 index q = ht*1024 + ks*64 + p*32 + l   (ht=0..15 tiles of 32 n-cols,
// ks=0..15 k16-steps, p=0..1 j-pairs, l=lane; g=l>>2, t=l&3).
// kb = ks*16 + 4t;  n0 = ht*32 + p*16 + g;  n1 = n0 + 8;  B[n][k] = W1[n>>7][k][n&127].
// Total 128 KB -> fully L1-resident per SM; mainloop reads it via LDG.128 (L1 hits).
__device__ __align__(16) uint4 g_B4[NHID * D_DIM / 8];   // 8192 uint4 = 128KB
__device__ __align__(16) float g_escore[N_MAX * 4];      // e = exp(score) per node/head

// score-kernel smem layout (bytes): b1 | w2 | score partials
#define SMB_B1    0
#define SMB_W2    2048
#define SMB_PART  4096                  // 4 heads x 128 tid x float4 = 8KB
#define SMB_TOT   12288

__device__ __forceinline__ uint32_t h2pack(float a, float b) {
    __half2 h = __floats2half2_rn(a, b);
    return *(uint32_t*)&h;
}

#define MMA_F16(cj, av, bx, by) \
    asm volatile( \
        "mma.sync.aligned.m16n8k16.row.col.f32.f16.f16.f32 " \
        "{%0,%1,%2,%3}, {%4,%5,%6,%7}, {%8,%9}, {%0,%1,%2,%3};" \
        : "+f"((cj)[0]), "+f"((cj)[1]), "+f"((cj)[2]), "+f"((cj)[3]) \
        : "r"((av).x), "r"((av).y), "r"((av).z), "r"((av).w), "r"(bx), "r"(by))

// ---------------- dummy kernel (profiling alignment: puts score at capture idx 3) ----
__global__ void mhap_dummy_kernel() {}

// ---------------- kernel 0: pack W1 -> fp16 fragment layout ----------------
__global__ void mhap_prep_kernel(const float* __restrict__ W1) {
    int q = blockIdx.x * blockDim.x + threadIdx.x;    // 8192 total
    if (q >= NHID * D_DIM / 8) return;
    int l  = q & 31;
    int p  = (q >> 5) & 1;
    int ks = (q >> 6) & 15;
    int ht = q >> 10;
    int g = l >> 2, t = l & 3;
    int n0 = ht * 32 + p * 16 + g;
    int n1 = n0 + 8;
    int kb = ks * 16 + 4 * t;
    #define B_EL(n, k) W1[((n) >> 7) * (D_DIM * 128) + (k) * 128 + ((n) & 127)]
    uint4 o;
    o.x = h2pack(B_EL(n0, kb),     B_EL(n0, kb + 1));
    o.y = h2pack(B_EL(n0, kb + 2), B_EL(n0, kb + 3));
    o.z = h2pack(B_EL(n1, kb),     B_EL(n1, kb + 1));
    o.w = h2pack(B_EL(n1, kb + 2), B_EL(n1, kb + 3));
    #undef B_EL
    g_B4[q] = o;
}

// ---------------- kernel 1: e-scores; warp owns m32; B via L1 LDG; barrier-free ----
__global__ void __launch_bounds__(T1, 2) mhap_score_kernel(
    const float* __restrict__ x,
    const float* __restrict__ b1g,
    const float* __restrict__ w2g,
    const float* __restrict__ b2g,
    int N)
{
    extern __shared__ float sm[];
    char* smc = (char*)sm;
    const int tid = threadIdx.x;
    const int w   = tid >> 5;
    const int l   = tid & 31;
    const int g   = l >> 2;
    const int t   = l & 3;
    const long node0 = (long)blockIdx.x * TM;

    // biases / W2 into smem; zero score partials
    for (int i = tid; i < NHID; i += T1) {
        ((float*)(smc + SMB_B1))[i] = b1g[i];
        ((float*)(smc + SMB_W2))[i] = w2g[i];
    }
    float4* s_part = (float4*)(smc + SMB_PART);   // [head*128 + tid] (private per thread)
    {
        float4 z = make_float4(0.f, 0.f, 0.f, 0.f);
        #pragma unroll
        for (int h = 0; h < 4; ++h) s_part[h * 128 + tid] = z;
    }

    // A fragments for TWO m16 tiles straight into registers (contiguous-k permuted)
    const long r0 = node0 + w * 32 + g;        // m-tile 0: rows g, g+8
    const long r1 = r0 + 8;
    const long r2 = r0 + 16;                   // m-tile 1: rows g+16, g+24
    const long r3 = r0 + 24;
    const bool v0 = r0 < N, v1 = r1 < N, v2 = r2 < N, v3 = r3 < N;
    uint4 a0[16], a1[16];
    #pragma unroll
    for (int ks = 0; ks < 16; ++ks) {
        int kb = ks * 16 + 4 * t;
        float4 f0 = make_float4(0.f, 0.f, 0.f, 0.f), f1 = f0, f2 = f0, f3 = f0;
        if (v0) f0 = *(const float4*)(x + r0 * D_DIM + kb);
        if (v1) f1 = *(const float4*)(x + r1 * D_DIM + kb);
        if (v2) f2 = *(const float4*)(x + r2 * D_DIM + kb);
        if (v3) f3 = *(const float4*)(x + r3 * D_DIM + kb);
        a0[ks].x = h2pack(f0.x, f0.y);  a0[ks].y = h2pack(f1.x, f1.y);
        a0[ks].z = h2pack(f0.z, f0.w);  a0[ks].w = h2pack(f1.z, f1.w);
        a1[ks].x = h2pack(f2.x, f2.y);  a1[ks].y = h2pack(f3.x, f3.y);
        a1[ks].z = h2pack(f2.z, f2.w);  a1[ks].w = h2pack(f3.z, f3.w);
    }
    __syncthreads();   // b1/w2 staged (the ONLY barrier in this kernel)

    const float* s_b1 = (const float*)(smc + SMB_B1);
    const float* s_w2 = (const float*)(smc + SMB_W2);

    for (int ht = 0; ht < 16; ++ht) {
        // B fragments straight from gmem (L1-resident after first touch)
        const uint4* Bg = g_B4 + ht * 1024 + l;

        float c0[4][4], c1[4][4];
        #pragma unroll
        for (int j = 0; j < 4; ++j) {
            c0[j][0] = c0[j][1] = c0[j][2] = c0[j][3] = 0.f;
            c1[j][0] = c1[j][1] = c1[j][2] = c1[j][3] = 0.f;
        }

        #pragma unroll 4
        for (int ks = 0; ks < 16; ++ks) {
            uint4 bA = __ldg(Bg + ks * 64);
            uint4 bB = __ldg(Bg + ks * 64 + 32);
            MMA_F16(c0[0], a0[ks], bA.x, bA.y);
            MMA_F16(c1[0], a1[ks], bA.x, bA.y);
            MMA_F16(c0[1], a0[ks], bA.z, bA.w);
            MMA_F16(c1[1], a1[ks], bA.z, bA.w);
            MMA_F16(c0[2], a0[ks], bB.x, bB.y);
            MMA_F16(c1[2], a1[ks], bB.x, bB.y);
            MMA_F16(c0[3], a0[ks], bB.z, bB.w);
            MMA_F16(c1[3], a1[ks], bB.z, bB.w);
        }

        // epilogue: relu + W2 dot for this tile's 32 hidden cols (head = ht>>2)
        float p0 = 0.f, p1 = 0.f, p2 = 0.f, p3 = 0.f;
        int nb = ht * 32 + 2 * t;
        #pragma unroll
        for (int j = 0; j < 4; ++j) {
            int n = nb + j * 8;
            float w2a = s_w2[n], w2b = s_w2[n + 1];
            float ba  = s_b1[n], bb = s_b1[n + 1];
            p0 += fmaxf(c0[j][0] + ba, 0.f) * w2a + fmaxf(c0[j][1] + bb, 0.f) * w2b;
            p1 += fmaxf(c0[j][2] + ba, 0.f) * w2a + fmaxf(c0[j][3] + bb, 0.f) * w2b;
            p2 += fmaxf(c1[j][0] + ba, 0.f) * w2a + fmaxf(c1[j][1] + bb, 0.f) * w2b;
            p3 += fmaxf(c1[j][2] + ba, 0.f) * w2a + fmaxf(c1[j][3] + bb, 0.f) * w2b;
        }
        // accumulate into smem partials (thread-private slots; no sync needed)
        {
            float4* sp = s_part + (ht >> 2) * 128 + tid;
            float4 v = *sp;
            v.x += p0; v.y += p1; v.z += p2; v.w += p3;
            *sp = v;
        }
    }

    // final: gather per-head partials, reduce over the 4 lanes sharing a row
    float4 P0 = s_part[0 * 128 + tid];   // heads 0..3 (x=row g, y=g+8, z=g+16, w=g+24)
    float4 P1 = s_part[1 * 128 + tid];
    float4 P2 = s_part[2 * 128 + tid];
    float4 P3 = s_part[3 * 128 + tid];
    #pragma unroll
    for (int off = 1; off <= 2; off <<= 1) {
        P0.x += __shfl_xor_sync(0xFFFFFFFFu, P0.x, off);
        P0.y += __shfl_xor_sync(0xFFFFFFFFu, P0.y, off);
        P0.z += __shfl_xor_sync(0xFFFFFFFFu, P0.z, off);
        P0.w += __shfl_xor_sync(0xFFFFFFFFu, P0.w, off);
        P1.x += __shfl_xor_sync(0xFFFFFFFFu, P1.x, off);
        P1.y += __shfl_xor_sync(0xFFFFFFFFu, P1.y, off);
        P1.z += __shfl_xor_sync(0xFFFFFFFFu, P1.z, off);
        P1.w += __shfl_xor_sync(0xFFFFFFFFu, P1.w, off);
        P2.x += __shfl_xor_sync(0xFFFFFFFFu, P2.x, off);
        P2.y += __shfl_xor_sync(0xFFFFFFFFu, P2.y, off);
        P2.z += __shfl_xor_sync(0xFFFFFFFFu, P2.z, off);
        P2.w += __shfl_xor_sync(0xFFFFFFFFu, P2.w, off);
        P3.x += __shfl_xor_sync(0xFFFFFFFFu, P3.x, off);
        P3.y += __shfl_xor_sync(0xFFFFFFFFu, P3.y, off);
        P3.z += __shfl_xor_sync(0xFFFFFFFFu, P3.z, off);
        P3.w += __shfl_xor_sync(0xFFFFFFFFu, P3.w, off);
    }
    if (t == 0) {
        // store e = exp(score) directly (softmax without max-shift: |score| << 80)
        float b20 = b2g[0], b21 = b2g[1], b22 = b2g[2], b23 = b2g[3];
        if (v0) {
            float4 o;
            o.x = __expf(P0.x + b20); o.y = __expf(P1.x + b21);
            o.z = __expf(P2.x + b22); o.w = __expf(P3.x + b23);
            *(float4*)(g_escore + r0 * 4) = o;
        }
        if (v1) {
            float4 o;
            o.x = __expf(P0.y + b20); o.y = __expf(P1.y + b21);
            o.z = __expf(P2.y + b22); o.w = __expf(P3.y + b23);
            *(float4*)(g_escore + r1 * 4) = o;
        }
        if (v2) {
            float4 o;
            o.x = __expf(P0.z + b20); o.y = __expf(P1.z + b21);
            o.z = __expf(P2.z + b22); o.w = __expf(P3.z + b23);
            *(float4*)(g_escore + r2 * 4) = o;
        }
        if (v3) {
            float4 o;
            o.x = __expf(P0.w + b20); o.y = __expf(P1.w + b21);
            o.z = __expf(P2.w + b22); o.w = __expf(P3.w + b23);
            *(float4*)(g_escore + r3 * 4) = o;
        }
    }
}

// ---------------- kernel 2: segment normalize + weighted segment-sum (R7 version) ---
__device__ __forceinline__ int lower_bound_i(const int* __restrict__ a, int n, int v) {
    int lo = 0, hi = n;
    while (lo < hi) { int mid = (lo + hi) >> 1; if (a[mid] < v) lo = mid + 1; else hi = mid; }
    return lo;
}

__global__ void __launch_bounds__(256) mhap_pool_kernel(
    const float* __restrict__ x, const int* __restrict__ seg,
    float* __restrict__ out, int N)
{
    const int g = blockIdx.x;
    const int tid = threadIdx.x;
    const int wid = tid >> 5, lid = tid & 31;
    __shared__ float s_red[8][4];
    __shared__ float s_inv[4];
    __shared__ float s_w[256];
    __shared__ float4 s_acc[256];
    __shared__ int s_bounds[2];

    if (tid == 0) s_bounds[0] = lower_bound_i(seg, N, g);
    if (tid == 32) s_bounds[1] = lower_bound_i(seg, N, g + 1);
    __syncthreads();
    const int lo = s_bounds[0], hi = s_bounds[1];

    if (lo >= hi) {                       // empty segment -> zeros
        out[(long)g * D_DIM + tid] = 0.f;
        return;
    }

    // ---- pass 1: per-head sum of e ----
    float t0 = 0.f, t1 = 0.f, t2 = 0.f, t3 = 0.f;
    for (int n = lo + tid; n < hi; n += 256) {
        float4 ev = *(const float4*)(g_escore + (long)n * 4);
        t0 += ev.x; t1 += ev.y; t2 += ev.z; t3 += ev.w;
    }
    #pragma unroll
    for (int off = 16; off; off >>= 1) {
        t0 += __shfl_xor_sync(0xFFFFFFFFu, t0, off);
        t1 += __shfl_xor_sync(0xFFFFFFFFu, t1, off);
        t2 += __shfl_xor_sync(0xFFFFFFFFu, t2, off);
        t3 += __shfl_xor_sync(0xFFFFFFFFu, t3, off);
    }
    if (lid == 0) { s_red[wid][0] = t0; s_red[wid][1] = t1; s_red[wid][2] = t2; s_red[wid][3] = t3; }
    __syncthreads();
    if (tid == 0) {
        float a0 = 0.f, a1 = 0.f, a2 = 0.f, a3 = 0.f;
        for (int ww = 0; ww < 8; ++ww) {
            a0 += s_red[ww][0]; a1 += s_red[ww][1]; a2 += s_red[ww][2]; a3 += s_red[ww][3];
        }
        s_inv[0] = 0.25f / a0; s_inv[1] = 0.25f / a1;
        s_inv[2] = 0.25f / a2; s_inv[3] = 0.25f / a3;
    }
    __syncthreads();
    const float i0 = s_inv[0], i1 = s_inv[1], i2 = s_inv[2], i3 = s_inv[3];

    // ---- pass 2: weighted sum; thread owns dims d4..d4+3, row-group rg ----
    const int d4 = (tid & 63) * 4;
    const int rg = tid >> 6;
    float4 a0 = make_float4(0.f, 0.f, 0.f, 0.f), a1 = a0, a2 = a0, a3 = a0;

    for (int base = lo; base < hi; base += 256) {
        int cnt = min(256, hi - base);
        __syncthreads();
        if (tid < cnt) {
            float4 ev = *(const float4*)(g_escore + (long)(base + tid) * 4);
            s_w[tid] = ev.x * i0 + ev.y * i1 + ev.z * i2 + ev.w * i3;
        }
        __syncthreads();
        const float* xb = x + (long)base * D_DIM + d4;
        int j = rg;
        for (; j + 12 < cnt; j += 16) {
            float w0 = s_w[j], w1 = s_w[j + 4], w2 = s_w[j + 8], w3 = s_w[j + 12];
            float4 x0 = *(const float4*)(xb + (long)j * D_DIM);
            float4 x1 = *(const float4*)(xb + (long)(j + 4) * D_DIM);
            float4 x2 = *(const float4*)(xb + (long)(j + 8) * D_DIM);
            float4 x3 = *(const float4*)(xb + (long)(j + 12) * D_DIM);
            a0.x = fmaf(w0, x0.x, a0.x); a0.y = fmaf(w0, x0.y, a0.y);
            a0.z = fmaf(w0, x0.z, a0.z); a0.w = fmaf(w0, x0.w, a0.w);
            a1.x = fmaf(w1, x1.x, a1.x); a1.y = fmaf(w1, x1.y, a1.y);
            a1.z = fmaf(w1, x1.z, a1.z); a1.w = fmaf(w1, x1.w, a1.w);
            a2.x = fmaf(w2, x2.x, a2.x); a2.y = fmaf(w2, x2.y, a2.y);
            a2.z = fmaf(w2, x2.z, a2.z); a2.w = fmaf(w2, x2.w, a2.w);
            a3.x = fmaf(w3, x3.x, a3.x); a3.y = fmaf(w3, x3.y, a3.y);
            a3.z = fmaf(w3, x3.z, a3.z); a3.w = fmaf(w3, x3.w, a3.w);
        }
        for (; j < cnt; j += 4) {
            float wv = s_w[j];
            float4 xv = *(const float4*)(xb + (long)j * D_DIM);
            a0.x = fmaf(wv, xv.x, a0.x); a0.y = fmaf(wv, xv.y, a0.y);
            a0.z = fmaf(wv, xv.z, a0.z); a0.w = fmaf(wv, xv.w, a0.w);
        }
    }

    a0.x = (a0.x + a1.x) + (a2.x + a3.x);
    a0.y = (a0.y + a1.y) + (a2.y + a3.y);
    a0.z = (a0.z + a1.z) + (a2.z + a3.z);
    a0.w = (a0.w + a1.w) + (a2.w + a3.w);
    s_acc[tid] = a0;
    __syncthreads();

    if (tid < 64) {
        float4 r0 = s_acc[tid],       r1 = s_acc[tid + 64];
        float4 r2 = s_acc[tid + 128], r3 = s_acc[tid + 192];
        float4 o;
        o.x = (r0.x + r1.x) + (r2.x + r3.x);
        o.y = (r0.y + r1.y) + (r2.y + r3.y);
        o.z = (r0.z + r1.z) + (r2.z + r3.z);
        o.w = (r0.w + r1.w) + (r2.w + r3.w);
        *(float4*)(out + (long)g * D_DIM + tid * 4) = o;
    }
}

// ---------------- launch ----------------
extern "C" void kernel_launch(void* const* d_in, const int* in_sizes, int n_in,
                              void* d_out, int out_size) {
    const float* x   = (const float*)d_in[0];
    const int*   seg = (const int*)d_in[1];
    int base = 2;
    if (n_in >= 7 && in_sizes[2] == 1) base = 3;   // skip num_graphs scalar if present
    const float* W1 = (const float*)d_in[base];
    const float* b1 = (const float*)d_in[base + 1];
    const float* W2 = (const float*)d_in[base + 2];
    const float* b2 = (const float*)d_in[base + 3];

    const int N = in_sizes[1];
    const int G = out_size / D_DIM;

    mhap_prep_kernel<<<(NHID * D_DIM / 8 + 255) / 256, 256>>>(W1);     // idx 0
    mhap_dummy_kernel<<<1, 1>>>();                                      // idx 1
    mhap_dummy_kernel<<<1, 1>>>();                                      // idx 2

    cudaFuncSetAttribute(mhap_score_kernel,
                         cudaFuncAttributeMaxDynamicSharedMemorySize, SMB_TOT);
    mhap_score_kernel<<<(N + TM - 1) / TM, T1, SMB_TOT>>>(x, b1, W2, b2, N);  // idx 3

    mhap_pool_kernel<<<G, 256>>>(x, seg, (float*)d_out, N);             // idx 4
}

// round 14
// speedup vs baseline: 1.1574x; 1.1574x over previous
#include <cuda_runtime.h>
#include <cuda_fp16.h>
#include <cstdint>

// ---------------- problem constants ----------------
#define D_DIM   256      // embedding dim = GEMM K
#define NHID    512      // H*K_hid = GEMM N
#define TM      256      // nodes per CTA (8 warps x m32)
#define T1      256      // threads in score kernel (8 warps)
#define N_MAX   200704

// g_B4: W1 transposed, fp16, mma-fragment packed with CONTIGUOUS-k permutation.
// uint4 index q = ht*1024 + ks*64 + p*32 + l   (ht=0..15 tiles of 32 n-cols,
// ks=0..15 k16-steps, p=0..1 j-pairs, l=lane; g=l>>2, t=l&3).
// kb = ks*16 + 4t;  n0 = ht*32 + p*16 + g;  n1 = n0 + 8;  B[n][k] = W1[n>>7][k][n&127].
// TOTAL: 16384 uint4 = 256 KB (2 halves of 8192 uint4 = 128 KB each).
__device__ __align__(16) uint4 g_B4[NHID * D_DIM / 8];
__device__ __align__(16) float g_escore[N_MAX * 4];      // e = exp(score) per node/head

// score-kernel smem layout (bytes): b1 | w2 | score partials | HALF-B buffer (128KB)
#define SMB_B1    0
#define SMB_W2    2048
#define SMB_PART  4096                  // 4 heads x 256 tid x float4 = 16KB
#define SMB_B     20480                 // 8192 uint4 = 128KB (one half of B)
#define SMB_TOT   151552                // 148KB -> 1 CTA/SM

__device__ __forceinline__ uint32_t h2pack(float a, float b) {
    __half2 h = __floats2half2_rn(a, b);
    return *(uint32_t*)&h;
}

__device__ __forceinline__ uint32_t smem_u32(const void* p) {
    uint32_t r;
    asm("{ .reg .u64 t; cvta.to.shared.u64 t, %1; cvt.u32.u64 %0, t; }" : "=r"(r) : "l"(p));
    return r;
}

__device__ __forceinline__ void cp16(uint32_t dst, const void* src) {
    asm volatile("cp.async.cg.shared.global [%0], [%1], 16;" :: "r"(dst), "l"(src));
}

// stage one 128KB half of B (8192 uint4); 32 cp16 per thread + commit
__device__ __forceinline__ void stage_half(uint32_t dst, const uint4* __restrict__ src, int tid) {
    #pragma unroll
    for (int e = 0; e < 32; ++e) {
        int qb = e * 256 + tid;
        cp16(dst + (uint32_t)qb * 16u, src + qb);
    }
    asm volatile("cp.async.commit_group;" ::: "memory");
}

#define MMA_F16(cj, av, bx, by) \
    asm volatile( \
        "mma.sync.aligned.m16n8k16.row.col.f32.f16.f16.f32 " \
        "{%0,%1,%2,%3}, {%4,%5,%6,%7}, {%8,%9}, {%0,%1,%2,%3};" \
        : "+f"((cj)[0]), "+f"((cj)[1]), "+f"((cj)[2]), "+f"((cj)[3]) \
        : "r"((av).x), "r"((av).y), "r"((av).z), "r"((av).w), "r"(bx), "r"(by))

// ---------------- dummy kernel (profiling alignment: puts score at capture idx 3) ----
__global__ void mhap_dummy_kernel() {}

// ---------------- kernel 0: pack W1 -> fp16 fragment layout ----------------
__global__ void mhap_prep_kernel(const float* __restrict__ W1) {
    int q = blockIdx.x * blockDim.x + threadIdx.x;    // 16384 total
    if (q >= NHID * D_DIM / 8) return;
    int l  = q & 31;
    int p  = (q >> 5) & 1;
    int ks = (q >> 6) & 15;
    int ht = q >> 10;
    int g = l >> 2, t = l & 3;
    int n0 = ht * 32 + p * 16 + g;
    int n1 = n0 + 8;
    int kb = ks * 16 + 4 * t;
    #define B_EL(n, k) W1[((n) >> 7) * (D_DIM * 128) + (k) * 128 + ((n) & 127)]
    uint4 o;
    o.x = h2pack(B_EL(n0, kb),     B_EL(n0, kb + 1));
    o.y = h2pack(B_EL(n0, kb + 2), B_EL(n0, kb + 3));
    o.z = h2pack(B_EL(n1, kb),     B_EL(n1, kb + 1));
    o.w = h2pack(B_EL(n1, kb + 2), B_EL(n1, kb + 3));
    #undef B_EL
    g_B4[q] = o;
}

// ---------------- kernel 1: e-scores; 8 warps x m32; two-phase half-B staging -------
__global__ void __launch_bounds__(T1, 1) mhap_score_kernel(
    const float* __restrict__ x,
    const float* __restrict__ b1g,
    const float* __restrict__ w2g,
    const float* __restrict__ b2g,
    int N)
{
    extern __shared__ float sm[];
    char* smc = (char*)sm;
    const int tid = threadIdx.x;
    const int w   = tid >> 5;
    const int l   = tid & 31;
    const int g   = l >> 2;
    const int t   = l & 3;
    const long node0 = (long)blockIdx.x * TM;
    const uint32_t smb = smem_u32(sm);

    // stage first half of B (tiles 0..7, 128 KB)
    stage_half(smb + SMB_B, g_B4, tid);

    // biases / W2 into smem; zero score partials
    for (int i = tid; i < NHID; i += T1) {
        ((float*)(smc + SMB_B1))[i] = b1g[i];
        ((float*)(smc + SMB_W2))[i] = w2g[i];
    }
    float4* s_part = (float4*)(smc + SMB_PART);   // [head*256 + tid] (thread-private)
    {
        float4 z = make_float4(0.f, 0.f, 0.f, 0.f);
        #pragma unroll
        for (int h = 0; h < 4; ++h) s_part[h * 256 + tid] = z;
    }

    // A fragments for TWO m16 tiles straight into registers (contiguous-k permuted)
    const long r0 = node0 + w * 32 + g;        // m-tile 0: rows g, g+8
    const long r1 = r0 + 8;
    const long r2 = r0 + 16;                   // m-tile 1: rows g+16, g+24
    const long r3 = r0 + 24;
    const bool v0 = r0 < N, v1 = r1 < N, v2 = r2 < N, v3 = r3 < N;
    uint4 a0[16], a1[16];
    #pragma unroll
    for (int ks = 0; ks < 16; ++ks) {
        int kb = ks * 16 + 4 * t;
        float4 f0 = make_float4(0.f, 0.f, 0.f, 0.f), f1 = f0, f2 = f0, f3 = f0;
        if (v0) f0 = *(const float4*)(x + r0 * D_DIM + kb);
        if (v1) f1 = *(const float4*)(x + r1 * D_DIM + kb);
        if (v2) f2 = *(const float4*)(x + r2 * D_DIM + kb);
        if (v3) f3 = *(const float4*)(x + r3 * D_DIM + kb);
        a0[ks].x = h2pack(f0.x, f0.y);  a0[ks].y = h2pack(f1.x, f1.y);
        a0[ks].z = h2pack(f0.z, f0.w);  a0[ks].w = h2pack(f1.z, f1.w);
        a1[ks].x = h2pack(f2.x, f2.y);  a1[ks].y = h2pack(f3.x, f3.y);
        a1[ks].z = h2pack(f2.z, f2.w);  a1[ks].w = h2pack(f3.z, f3.w);
    }

    const float* s_b1 = (const float*)(smc + SMB_B1);
    const float* s_w2 = (const float*)(smc + SMB_W2);

    for (int ph = 0; ph < 2; ++ph) {
        asm volatile("cp.async.wait_group 0;" ::: "memory");
        __syncthreads();                       // this half of B staged & visible

        for (int ht2 = 0; ht2 < 8; ++ht2) {
            const int ht = ph * 8 + ht2;
            const uint4* Bu = (const uint4*)(smc + SMB_B) + ht2 * 1024 + l;

            float c0[4][4], c1[4][4];
            #pragma unroll
            for (int j = 0; j < 4; ++j) {
                c0[j][0] = c0[j][1] = c0[j][2] = c0[j][3] = 0.f;
                c1[j][0] = c1[j][1] = c1[j][2] = c1[j][3] = 0.f;
            }

            #pragma unroll
            for (int ks = 0; ks < 16; ++ks) {
                uint4 bA = Bu[ks * 64];
                uint4 bB = Bu[ks * 64 + 32];
                MMA_F16(c0[0], a0[ks], bA.x, bA.y);
                MMA_F16(c1[0], a1[ks], bA.x, bA.y);
                MMA_F16(c0[1], a0[ks], bA.z, bA.w);
                MMA_F16(c1[1], a1[ks], bA.z, bA.w);
                MMA_F16(c0[2], a0[ks], bB.x, bB.y);
                MMA_F16(c1[2], a1[ks], bB.x, bB.y);
                MMA_F16(c0[3], a0[ks], bB.z, bB.w);
                MMA_F16(c1[3], a1[ks], bB.z, bB.w);
            }

            // epilogue: relu + W2 dot for this tile's 32 hidden cols (head = ht>>2)
            float p0 = 0.f, p1 = 0.f, p2 = 0.f, p3 = 0.f;
            int nb = ht * 32 + 2 * t;
            #pragma unroll
            for (int j = 0; j < 4; ++j) {
                int n = nb + j * 8;
                float w2a = s_w2[n], w2b = s_w2[n + 1];
                float ba  = s_b1[n], bb = s_b1[n + 1];
                p0 += fmaxf(c0[j][0] + ba, 0.f) * w2a + fmaxf(c0[j][1] + bb, 0.f) * w2b;
                p1 += fmaxf(c0[j][2] + ba, 0.f) * w2a + fmaxf(c0[j][3] + bb, 0.f) * w2b;
                p2 += fmaxf(c1[j][0] + ba, 0.f) * w2a + fmaxf(c1[j][1] + bb, 0.f) * w2b;
                p3 += fmaxf(c1[j][2] + ba, 0.f) * w2a + fmaxf(c1[j][3] + bb, 0.f) * w2b;
            }
            // accumulate into smem partials (thread-private slots; no sync needed)
            {
                float4* sp = s_part + (ht >> 2) * 256 + tid;
                float4 v = *sp;
                v.x += p0; v.y += p1; v.z += p2; v.w += p3;
                *sp = v;
            }
        }

        if (ph == 0) {
            __syncthreads();                   // all warps done reading half 0
            stage_half(smb + SMB_B, g_B4 + 8192, tid);   // tiles 8..15
        }
    }

    // final: gather per-head partials, reduce over the 4 lanes sharing a row
    float4 P0 = s_part[0 * 256 + tid];   // heads 0..3 (x=row g, y=g+8, z=g+16, w=g+24)
    float4 P1 = s_part[1 * 256 + tid];
    float4 P2 = s_part[2 * 256 + tid];
    float4 P3 = s_part[3 * 256 + tid];
    #pragma unroll
    for (int off = 1; off <= 2; off <<= 1) {
        P0.x += __shfl_xor_sync(0xFFFFFFFFu, P0.x, off);
        P0.y += __shfl_xor_sync(0xFFFFFFFFu, P0.y, off);
        P0.z += __shfl_xor_sync(0xFFFFFFFFu, P0.z, off);
        P0.w += __shfl_xor_sync(0xFFFFFFFFu, P0.w, off);
        P1.x += __shfl_xor_sync(0xFFFFFFFFu, P1.x, off);
        P1.y += __shfl_xor_sync(0xFFFFFFFFu, P1.y, off);
        P1.z += __shfl_xor_sync(0xFFFFFFFFu, P1.z, off);
        P1.w += __shfl_xor_sync(0xFFFFFFFFu, P1.w, off);
        P2.x += __shfl_xor_sync(0xFFFFFFFFu, P2.x, off);
        P2.y += __shfl_xor_sync(0xFFFFFFFFu, P2.y, off);
        P2.z += __shfl_xor_sync(0xFFFFFFFFu, P2.z, off);
        P2.w += __shfl_xor_sync(0xFFFFFFFFu, P2.w, off);
        P3.x += __shfl_xor_sync(0xFFFFFFFFu, P3.x, off);
        P3.y += __shfl_xor_sync(0xFFFFFFFFu, P3.y, off);
        P3.z += __shfl_xor_sync(0xFFFFFFFFu, P3.z, off);
        P3.w += __shfl_xor_sync(0xFFFFFFFFu, P3.w, off);
    }
    if (t == 0) {
        // store e = exp(score) directly (softmax without max-shift: |score| << 80)
        float b20 = b2g[0], b21 = b2g[1], b22 = b2g[2], b23 = b2g[3];
        if (v0) {
            float4 o;
            o.x = __expf(P0.x + b20); o.y = __expf(P1.x + b21);
            o.z = __expf(P2.x + b22); o.w = __expf(P3.x + b23);
            *(float4*)(g_escore + r0 * 4) = o;
        }
        if (v1) {
            float4 o;
            o.x = __expf(P0.y + b20); o.y = __expf(P1.y + b21);
            o.z = __expf(P2.y + b22); o.w = __expf(P3.y + b23);
            *(float4*)(g_escore + r1 * 4) = o;
        }
        if (v2) {
            float4 o;
            o.x = __expf(P0.z + b20); o.y = __expf(P1.z + b21);
            o.z = __expf(P2.z + b22); o.w = __expf(P3.z + b23);
            *(float4*)(g_escore + r2 * 4) = o;
        }
        if (v3) {
            float4 o;
            o.x = __expf(P0.w + b20); o.y = __expf(P1.w + b21);
            o.z = __expf(P2.w + b22); o.w = __expf(P3.w + b23);
            *(float4*)(g_escore + r3 * 4) = o;
        }
    }
}

// ---------------- kernel 2: segment normalize + weighted segment-sum (R7 version) ---
__device__ __forceinline__ int lower_bound_i(const int* __restrict__ a, int n, int v) {
    int lo = 0, hi = n;
    while (lo < hi) { int mid = (lo + hi) >> 1; if (a[mid] < v) lo = mid + 1; else hi = mid; }
    return lo;
}

__global__ void __launch_bounds__(256) mhap_pool_kernel(
    const float* __restrict__ x, const int* __restrict__ seg,
    float* __restrict__ out, int N)
{
    const int g = blockIdx.x;
    const int tid = threadIdx.x;
    const int wid = tid >> 5, lid = tid & 31;
    __shared__ float s_red[8][4];
    __shared__ float s_inv[4];
    __shared__ float s_w[256];
    __shared__ float4 s_acc[256];
    __shared__ int s_bounds[2];

    if (tid == 0) s_bounds[0] = lower_bound_i(seg, N, g);
    if (tid == 32) s_bounds[1] = lower_bound_i(seg, N, g + 1);
    __syncthreads();
    const int lo = s_bounds[0], hi = s_bounds[1];

    if (lo >= hi) {                       // empty segment -> zeros
        out[(long)g * D_DIM + tid] = 0.f;
        return;
    }

    // ---- pass 1: per-head sum of e ----
    float t0 = 0.f, t1 = 0.f, t2 = 0.f, t3 = 0.f;
    for (int n = lo + tid; n < hi; n += 256) {
        float4 ev = *(const float4*)(g_escore + (long)n * 4);
        t0 += ev.x; t1 += ev.y; t2 += ev.z; t3 += ev.w;
    }
    #pragma unroll
    for (int off = 16; off; off >>= 1) {
        t0 += __shfl_xor_sync(0xFFFFFFFFu, t0, off);
        t1 += __shfl_xor_sync(0xFFFFFFFFu, t1, off);
        t2 += __shfl_xor_sync(0xFFFFFFFFu, t2, off);
        t3 += __shfl_xor_sync(0xFFFFFFFFu, t3, off);
    }
    if (lid == 0) { s_red[wid][0] = t0; s_red[wid][1] = t1; s_red[wid][2] = t2; s_red[wid][3] = t3; }
    __syncthreads();
    if (tid == 0) {
        float a0 = 0.f, a1 = 0.f, a2 = 0.f, a3 = 0.f;
        for (int ww = 0; ww < 8; ++ww) {
            a0 += s_red[ww][0]; a1 += s_red[ww][1]; a2 += s_red[ww][2]; a3 += s_red[ww][3];
        }
        s_inv[0] = 0.25f / a0; s_inv[1] = 0.25f / a1;
        s_inv[2] = 0.25f / a2; s_inv[3] = 0.25f / a3;
    }
    __syncthreads();
    const float i0 = s_inv[0], i1 = s_inv[1], i2 = s_inv[2], i3 = s_inv[3];

    // ---- pass 2: weighted sum; thread owns dims d4..d4+3, row-group rg ----
    const int d4 = (tid & 63) * 4;
    const int rg = tid >> 6;
    float4 a0 = make_float4(0.f, 0.f, 0.f, 0.f), a1 = a0, a2 = a0, a3 = a0;

    for (int base = lo; base < hi; base += 256) {
        int cnt = min(256, hi - base);
        __syncthreads();
        if (tid < cnt) {
            float4 ev = *(const float4*)(g_escore + (long)(base + tid) * 4);
            s_w[tid] = ev.x * i0 + ev.y * i1 + ev.z * i2 + ev.w * i3;
        }
        __syncthreads();
        const float* xb = x + (long)base * D_DIM + d4;
        int j = rg;
        for (; j + 12 < cnt; j += 16) {
            float w0 = s_w[j], w1 = s_w[j + 4], w2 = s_w[j + 8], w3 = s_w[j + 12];
            float4 x0 = *(const float4*)(xb + (long)j * D_DIM);
            float4 x1 = *(const float4*)(xb + (long)(j + 4) * D_DIM);
            float4 x2 = *(const float4*)(xb + (long)(j + 8) * D_DIM);
            float4 x3 = *(const float4*)(xb + (long)(j + 12) * D_DIM);
            a0.x = fmaf(w0, x0.x, a0.x); a0.y = fmaf(w0, x0.y, a0.y);
            a0.z = fmaf(w0, x0.z, a0.z); a0.w = fmaf(w0, x0.w, a0.w);
            a1.x = fmaf(w1, x1.x, a1.x); a1.y = fmaf(w1, x1.y, a1.y);
            a1.z = fmaf(w1, x1.z, a1.z); a1.w = fmaf(w1, x1.w, a1.w);
            a2.x = fmaf(w2, x2.x, a2.x); a2.y = fmaf(w2, x2.y, a2.y);
            a2.z = fmaf(w2, x2.z, a2.z); a2.w = fmaf(w2, x2.w, a2.w);
            a3.x = fmaf(w3, x3.x, a3.x); a3.y = fmaf(w3, x3.y, a3.y);
            a3.z = fmaf(w3, x3.z, a3.z); a3.w = fmaf(w3, x3.w, a3.w);
        }
        for (; j < cnt; j += 4) {
            float wv = s_w[j];
            float4 xv = *(const float4*)(xb + (long)j * D_DIM);
            a0.x = fmaf(wv, xv.x, a0.x); a0.y = fmaf(wv, xv.y, a0.y);
            a0.z = fmaf(wv, xv.z, a0.z); a0.w = fmaf(wv, xv.w, a0.w);
        }
    }

    a0.x = (a0.x + a1.x) + (a2.x + a3.x);
    a0.y = (a0.y + a1.y) + (a2.y + a3.y);
    a0.z = (a0.z + a1.z) + (a2.z + a3.z);
    a0.w = (a0.w + a1.w) + (a2.w + a3.w);
    s_acc[tid] = a0;
    __syncthreads();

    if (tid < 64) {
        float4 r0 = s_acc[tid],       r1 = s_acc[tid + 64];
        float4 r2 = s_acc[tid + 128], r3 = s_acc[tid + 192];
        float4 o;
        o.x = (r0.x + r1.x) + (r2.x + r3.x);
        o.y = (r0.y + r1.y) + (r2.y + r3.y);
        o.z = (r0.z + r1.z) + (r2.z + r3.z);
        o.w = (r0.w + r1.w) + (r2.w + r3.w);
        *(float4*)(out + (long)g * D_DIM + tid * 4) = o;
    }
}

// ---------------- launch ----------------
extern "C" void kernel_launch(void* const* d_in, const int* in_sizes, int n_in,
                              void* d_out, int out_size) {
    const float* x   = (const float*)d_in[0];
    const int*   seg = (const int*)d_in[1];
    int base = 2;
    if (n_in >= 7 && in_sizes[2] == 1) base = 3;   // skip num_graphs scalar if present
    const float* W1 = (const float*)d_in[base];
    const float* b1 = (const float*)d_in[base + 1];
    const float* W2 = (const float*)d_in[base + 2];
    const float* b2 = (const float*)d_in[base + 3];

    const int N = in_sizes[1];
    const int G = out_size / D_DIM;

    mhap_prep_kernel<<<(NHID * D_DIM / 8 + 255) / 256, 256>>>(W1);     // idx 0
    mhap_dummy_kernel<<<1, 1>>>();                                      // idx 1
    mhap_dummy_kernel<<<1, 1>>>();                                      // idx 2

    cudaFuncSetAttribute(mhap_score_kernel,
                         cudaFuncAttributeMaxDynamicSharedMemorySize, SMB_TOT);
    mhap_score_kernel<<<(N + TM - 1) / TM, T1, SMB_TOT>>>(x, b1, W2, b2, N);  // idx 3

    mhap_pool_kernel<<<G, 256>>>(x, seg, (float*)d_out, N);             // idx 4
}

// round 15
// speedup vs baseline: 1.3435x; 1.1607x over previous
#include <cuda_runtime.h>
#include <cuda_fp16.h>
#include <cstdint>

// ---------------- problem constants ----------------
#define D_DIM   256      // embedding dim = GEMM K
#define NHID    512      // H*K_hid = GEMM N
#define TM      128      // nodes per CTA (4 warps x m32)
#define T1      128      // threads in score kernel (4 warps)
#define N_MAX   200704

// g_B4: W1 transposed, fp16, mma-fragment packed with CONTIGUOUS-k permutation.
// uint4 index q = ht*1024 + ks*64 + p*32 + l   (ht=0..15 tiles of 32 n-cols,
// ks=0..15 k16-steps, p=0..1 j-pairs, l=lane; g=l>>2, t=l&3).
// kb = ks*16 + 4t;  n0 = ht*32 + p*16 + g;  n1 = n0 + 8;  B[n][k] = W1[n>>7][k][n&127].
// TOTAL: 16384 uint4 = 256 KB.
__device__ __align__(16) uint4 g_B4[NHID * D_DIM / 8];
__device__ __align__(16) float g_escore[N_MAX * 4];      // e = exp(score) per node/head

// score-kernel smem layout (bytes): b1 | w2 | score partials | B triple buffer
#define SMB_B1    0
#define SMB_W2    2048
#define SMB_PART  4096                  // 4 heads x 128 tid x float4 = 8KB
#define SMB_BUF   12288                 // 3 x 16KB
#define SMB_TOT   61440                 // 60KB -> 2 CTAs/SM

__device__ __forceinline__ uint32_t h2pack(float a, float b) {
    __half2 h = __floats2half2_rn(a, b);
    return *(uint32_t*)&h;
}

__device__ __forceinline__ uint32_t smem_u32(const void* p) {
    uint32_t r;
    asm("{ .reg .u64 t; cvta.to.shared.u64 t, %1; cvt.u32.u64 %0, t; }" : "=r"(r) : "l"(p));
    return r;
}

__device__ __forceinline__ void cp16(uint32_t dst, const void* src) {
    asm volatile("cp.async.cg.shared.global [%0], [%1], 16;" :: "r"(dst), "l"(src));
}

#define MMA_F16(cj, av, bx, by) \
    asm volatile( \
        "mma.sync.aligned.m16n8k16.row.col.f32.f16.f16.f32 " \
        "{%0,%1,%2,%3}, {%4,%5,%6,%7}, {%8,%9}, {%0,%1,%2,%3};" \
        : "+f"((cj)[0]), "+f"((cj)[1]), "+f"((cj)[2]), "+f"((cj)[3]) \
        : "r"((av).x), "r"((av).y), "r"((av).z), "r"((av).w), "r"(bx), "r"(by))

// ---------------- dummy kernel (profiling alignment: puts pool at capture idx 3) ----
__global__ void mhap_dummy_kernel() {}

// ---------------- kernel 0: pack W1 -> fp16 fragment layout ----------------
__global__ void mhap_prep_kernel(const float* __restrict__ W1) {
    int q = blockIdx.x * blockDim.x + threadIdx.x;    // 16384 total
    if (q >= NHID * D_DIM / 8) return;
    int l  = q & 31;
    int p  = (q >> 5) & 1;
    int ks = (q >> 6) & 15;
    int ht = q >> 10;
    int g = l >> 2, t = l & 3;
    int n0 = ht * 32 + p * 16 + g;
    int n1 = n0 + 8;
    int kb = ks * 16 + 4 * t;
    #define B_EL(n, k) W1[((n) >> 7) * (D_DIM * 128) + (k) * 128 + ((n) & 127)]
    uint4 o;
    o.x = h2pack(B_EL(n0, kb),     B_EL(n0, kb + 1));
    o.y = h2pack(B_EL(n0, kb + 2), B_EL(n0, kb + 3));
    o.z = h2pack(B_EL(n1, kb),     B_EL(n1, kb + 1));
    o.w = h2pack(B_EL(n1, kb + 2), B_EL(n1, kb + 3));
    #undef B_EL
    g_B4[q] = o;
}

// ---------------- kernel 1: e-scores (exact R11 revert: best known, 142.8us) --------
__global__ void __launch_bounds__(T1, 2) mhap_score_kernel(
    const float* __restrict__ x,
    const float* __restrict__ b1g,
    const float* __restrict__ w2g,
    const float* __restrict__ b2g,
    int N)
{
    extern __shared__ float sm[];
    char* smc = (char*)sm;
    const int tid = threadIdx.x;
    const int w   = tid >> 5;
    const int l   = tid & 31;
    const int g   = l >> 2;
    const int t   = l & 3;
    const long node0 = (long)blockIdx.x * TM;
    const uint32_t smb = smem_u32(sm);

    // prefetch B tiles 0 and 1 (16 KB = 1024 uint4 each; 8 cp16 per thread)
    {
        uint32_t d0 = smb + SMB_BUF;
        #pragma unroll
        for (int e = 0; e < 8; ++e) {
            int qb = e * 128 + tid;
            cp16(d0 + (uint32_t)qb * 16u, g_B4 + qb);
        }
        asm volatile("cp.async.commit_group;" ::: "memory");
        #pragma unroll
        for (int e = 0; e < 8; ++e) {
            int qb = e * 128 + tid;
            cp16(d0 + 16384u + (uint32_t)qb * 16u, g_B4 + 1024 + qb);
        }
        asm volatile("cp.async.commit_group;" ::: "memory");
    }

    // biases / W2 into smem; zero score partials
    for (int i = tid; i < NHID; i += T1) {
        ((float*)(smc + SMB_B1))[i] = b1g[i];
        ((float*)(smc + SMB_W2))[i] = w2g[i];
    }
    float4* s_part = (float4*)(smc + SMB_PART);   // [head*128 + tid]
    {
        float4 z = make_float4(0.f, 0.f, 0.f, 0.f);
        #pragma unroll
        for (int h = 0; h < 4; ++h) s_part[h * 128 + tid] = z;
    }

    // A fragments for TWO m16 tiles straight into registers (contiguous-k permuted)
    const long r0 = node0 + w * 32 + g;        // m-tile 0: rows g, g+8
    const long r1 = r0 + 8;
    const long r2 = r0 + 16;                   // m-tile 1: rows g+16, g+24
    const long r3 = r0 + 24;
    const bool v0 = r0 < N, v1 = r1 < N, v2 = r2 < N, v3 = r3 < N;
    uint4 a0[16], a1[16];
    #pragma unroll
    for (int ks = 0; ks < 16; ++ks) {
        int kb = ks * 16 + 4 * t;
        float4 f0 = make_float4(0.f, 0.f, 0.f, 0.f), f1 = f0, f2 = f0, f3 = f0;
        if (v0) f0 = *(const float4*)(x + r0 * D_DIM + kb);
        if (v1) f1 = *(const float4*)(x + r1 * D_DIM + kb);
        if (v2) f2 = *(const float4*)(x + r2 * D_DIM + kb);
        if (v3) f3 = *(const float4*)(x + r3 * D_DIM + kb);
        a0[ks].x = h2pack(f0.x, f0.y);  a0[ks].y = h2pack(f1.x, f1.y);
        a0[ks].z = h2pack(f0.z, f0.w);  a0[ks].w = h2pack(f1.z, f1.w);
        a1[ks].x = h2pack(f2.x, f2.y);  a1[ks].y = h2pack(f3.x, f3.y);
        a1[ks].z = h2pack(f2.z, f2.w);  a1[ks].w = h2pack(f3.z, f3.w);
    }
    __syncthreads();   // s_part zeroed, b1/w2 staged

    const float* s_b1 = (const float*)(smc + SMB_B1);
    const float* s_w2 = (const float*)(smc + SMB_W2);

    for (int ht = 0; ht < 16; ++ht) {
        if (ht < 15) asm volatile("cp.async.wait_group 1;" ::: "memory");
        else         asm volatile("cp.async.wait_group 0;" ::: "memory");
        __syncthreads();   // single barrier: tile ht arrived; buffer (ht+2)%3 free

        // prefetch tile ht+2 into buffer (ht+2)%3 (consumed in iteration ht-1)
        int nxt = ht + 2;
        if (nxt < 16) {
            const uint4* src = g_B4 + nxt * 1024;
            uint32_t dstb = smb + SMB_BUF + (uint32_t)(nxt % 3) * 16384u;
            #pragma unroll
            for (int e = 0; e < 8; ++e) {
                int qb = e * 128 + tid;
                cp16(dstb + (uint32_t)qb * 16u, src + qb);
            }
            asm volatile("cp.async.commit_group;" ::: "memory");
        }

        const uint4* Bu = (const uint4*)(smc + SMB_BUF) + (ht % 3) * 1024 + l;

        float c0[4][4], c1[4][4];
        #pragma unroll
        for (int j = 0; j < 4; ++j) {
            c0[j][0] = c0[j][1] = c0[j][2] = c0[j][3] = 0.f;
            c1[j][0] = c1[j][1] = c1[j][2] = c1[j][3] = 0.f;
        }

        #pragma unroll
        for (int ks = 0; ks < 16; ++ks) {
            uint4 bA = Bu[ks * 64];
            uint4 bB = Bu[ks * 64 + 32];
            MMA_F16(c0[0], a0[ks], bA.x, bA.y);
            MMA_F16(c1[0], a1[ks], bA.x, bA.y);
            MMA_F16(c0[1], a0[ks], bA.z, bA.w);
            MMA_F16(c1[1], a1[ks], bA.z, bA.w);
            MMA_F16(c0[2], a0[ks], bB.x, bB.y);
            MMA_F16(c1[2], a1[ks], bB.x, bB.y);
            MMA_F16(c0[3], a0[ks], bB.z, bB.w);
            MMA_F16(c1[3], a1[ks], bB.z, bB.w);
        }

        // epilogue: relu + W2 dot for this tile's 32 hidden cols (head = ht>>2)
        float p0 = 0.f, p1 = 0.f, p2 = 0.f, p3 = 0.f;
        int nb = ht * 32 + 2 * t;
        #pragma unroll
        for (int j = 0; j < 4; ++j) {
            int n = nb + j * 8;
            float w2a = s_w2[n], w2b = s_w2[n + 1];
            float ba  = s_b1[n], bb = s_b1[n + 1];
            p0 += fmaxf(c0[j][0] + ba, 0.f) * w2a + fmaxf(c0[j][1] + bb, 0.f) * w2b;
            p1 += fmaxf(c0[j][2] + ba, 0.f) * w2a + fmaxf(c0[j][3] + bb, 0.f) * w2b;
            p2 += fmaxf(c1[j][0] + ba, 0.f) * w2a + fmaxf(c1[j][1] + bb, 0.f) * w2b;
            p3 += fmaxf(c1[j][2] + ba, 0.f) * w2a + fmaxf(c1[j][3] + bb, 0.f) * w2b;
        }
        // accumulate into smem partials (thread-private slots; no sync needed)
        {
            float4* sp = s_part + (ht >> 2) * 128 + tid;
            float4 v = *sp;
            v.x += p0; v.y += p1; v.z += p2; v.w += p3;
            *sp = v;
        }
    }

    // final: gather per-head partials, reduce over the 4 lanes sharing a row
    float4 P0 = s_part[0 * 128 + tid];   // heads 0..3 (x=row g, y=g+8, z=g+16, w=g+24)
    float4 P1 = s_part[1 * 128 + tid];
    float4 P2 = s_part[2 * 128 + tid];
    float4 P3 = s_part[3 * 128 + tid];
    #pragma unroll
    for (int off = 1; off <= 2; off <<= 1) {
        P0.x += __shfl_xor_sync(0xFFFFFFFFu, P0.x, off);
        P0.y += __shfl_xor_sync(0xFFFFFFFFu, P0.y, off);
        P0.z += __shfl_xor_sync(0xFFFFFFFFu, P0.z, off);
        P0.w += __shfl_xor_sync(0xFFFFFFFFu, P0.w, off);
        P1.x += __shfl_xor_sync(0xFFFFFFFFu, P1.x, off);
        P1.y += __shfl_xor_sync(0xFFFFFFFFu, P1.y, off);
        P1.z += __shfl_xor_sync(0xFFFFFFFFu, P1.z, off);
        P1.w += __shfl_xor_sync(0xFFFFFFFFu, P1.w, off);
        P2.x += __shfl_xor_sync(0xFFFFFFFFu, P2.x, off);
        P2.y += __shfl_xor_sync(0xFFFFFFFFu, P2.y, off);
        P2.z += __shfl_xor_sync(0xFFFFFFFFu, P2.z, off);
        P2.w += __shfl_xor_sync(0xFFFFFFFFu, P2.w, off);
        P3.x += __shfl_xor_sync(0xFFFFFFFFu, P3.x, off);
        P3.y += __shfl_xor_sync(0xFFFFFFFFu, P3.y, off);
        P3.z += __shfl_xor_sync(0xFFFFFFFFu, P3.z, off);
        P3.w += __shfl_xor_sync(0xFFFFFFFFu, P3.w, off);
    }
    if (t == 0) {
        // store e = exp(score) directly (softmax without max-shift: |score| << 80)
        float b20 = b2g[0], b21 = b2g[1], b22 = b2g[2], b23 = b2g[3];
        if (v0) {
            float4 o;
            o.x = __expf(P0.x + b20); o.y = __expf(P1.x + b21);
            o.z = __expf(P2.x + b22); o.w = __expf(P3.x + b23);
            *(float4*)(g_escore + r0 * 4) = o;
        }
        if (v1) {
            float4 o;
            o.x = __expf(P0.y + b20); o.y = __expf(P1.y + b21);
            o.z = __expf(P2.y + b22); o.w = __expf(P3.y + b23);
            *(float4*)(g_escore + r1 * 4) = o;
        }
        if (v2) {
            float4 o;
            o.x = __expf(P0.z + b20); o.y = __expf(P1.z + b21);
            o.z = __expf(P2.z + b22); o.w = __expf(P3.z + b23);
            *(float4*)(g_escore + r2 * 4) = o;
        }
        if (v3) {
            float4 o;
            o.x = __expf(P0.w + b20); o.y = __expf(P1.w + b21);
            o.z = __expf(P2.w + b22); o.w = __expf(P3.w + b23);
            *(float4*)(g_escore + r3 * 4) = o;
        }
    }
}

// ---------------- kernel 2: pool with deeper MLP (8 LDG.128 in flight) --------------
__device__ __forceinline__ int lower_bound_i(const int* __restrict__ a, int n, int v) {
    int lo = 0, hi = n;
    while (lo < hi) { int mid = (lo + hi) >> 1; if (a[mid] < v) lo = mid + 1; else hi = mid; }
    return lo;
}

__global__ void __launch_bounds__(256) mhap_pool_kernel(
    const float* __restrict__ x, const int* __restrict__ seg,
    float* __restrict__ out, int N)
{
    const int g = blockIdx.x;
    const int tid = threadIdx.x;
    const int wid = tid >> 5, lid = tid & 31;
    __shared__ float s_red[8][4];
    __shared__ float s_inv[4];
    __shared__ float s_w[256];
    __shared__ float4 s_acc[256];
    __shared__ int s_bounds[2];

    if (tid == 0) s_bounds[0] = lower_bound_i(seg, N, g);
    if (tid == 32) s_bounds[1] = lower_bound_i(seg, N, g + 1);
    __syncthreads();
    const int lo = s_bounds[0], hi = s_bounds[1];

    if (lo >= hi) {                       // empty segment -> zeros
        out[(long)g * D_DIM + tid] = 0.f;
        return;
    }

    // ---- pass 1: per-head sum of e ----
    float t0 = 0.f, t1 = 0.f, t2 = 0.f, t3 = 0.f;
    for (int n = lo + tid; n < hi; n += 256) {
        float4 ev = *(const float4*)(g_escore + (long)n * 4);
        t0 += ev.x; t1 += ev.y; t2 += ev.z; t3 += ev.w;
    }
    #pragma unroll
    for (int off = 16; off; off >>= 1) {
        t0 += __shfl_xor_sync(0xFFFFFFFFu, t0, off);
        t1 += __shfl_xor_sync(0xFFFFFFFFu, t1, off);
        t2 += __shfl_xor_sync(0xFFFFFFFFu, t2, off);
        t3 += __shfl_xor_sync(0xFFFFFFFFu, t3, off);
    }
    if (lid == 0) { s_red[wid][0] = t0; s_red[wid][1] = t1; s_red[wid][2] = t2; s_red[wid][3] = t3; }
    __syncthreads();
    if (tid == 0) {
        float a0 = 0.f, a1 = 0.f, a2 = 0.f, a3 = 0.f;
        for (int ww = 0; ww < 8; ++ww) {
            a0 += s_red[ww][0]; a1 += s_red[ww][1]; a2 += s_red[ww][2]; a3 += s_red[ww][3];
        }
        s_inv[0] = 0.25f / a0; s_inv[1] = 0.25f / a1;
        s_inv[2] = 0.25f / a2; s_inv[3] = 0.25f / a3;
    }
    __syncthreads();
    const float i0 = s_inv[0], i1 = s_inv[1], i2 = s_inv[2], i3 = s_inv[3];

    // ---- pass 2: weighted sum; thread owns dims d4..d4+3, row-group rg; 8-deep MLP --
    const int d4 = (tid & 63) * 4;
    const int rg = tid >> 6;
    float4 a0 = make_float4(0.f, 0.f, 0.f, 0.f), a1 = a0, a2 = a0, a3 = a0;

    for (int base = lo; base < hi; base += 256) {
        int cnt = min(256, hi - base);
        __syncthreads();
        if (tid < cnt) {
            float4 ev = *(const float4*)(g_escore + (long)(base + tid) * 4);
            s_w[tid] = ev.x * i0 + ev.y * i1 + ev.z * i2 + ev.w * i3;
        }
        __syncthreads();
        const float* xb = x + (long)base * D_DIM + d4;
        int j = rg;
        // 32 rows/iter: 8 LDG.128 in flight per thread
        for (; j + 28 < cnt; j += 32) {
            float4 x0 = *(const float4*)(xb + (long)j * D_DIM);
            float4 x1 = *(const float4*)(xb + (long)(j + 4) * D_DIM);
            float4 x2 = *(const float4*)(xb + (long)(j + 8) * D_DIM);
            float4 x3 = *(const float4*)(xb + (long)(j + 12) * D_DIM);
            float4 x4 = *(const float4*)(xb + (long)(j + 16) * D_DIM);
            float4 x5 = *(const float4*)(xb + (long)(j + 20) * D_DIM);
            float4 x6 = *(const float4*)(xb + (long)(j + 24) * D_DIM);
            float4 x7 = *(const float4*)(xb + (long)(j + 28) * D_DIM);
            float w0 = s_w[j],      w1 = s_w[j + 4],  w2 = s_w[j + 8],  w3 = s_w[j + 12];
            float w4 = s_w[j + 16], w5 = s_w[j + 20], w6 = s_w[j + 24], w7 = s_w[j + 28];
            a0.x = fmaf(w0, x0.x, a0.x); a0.y = fmaf(w0, x0.y, a0.y);
            a0.z = fmaf(w0, x0.z, a0.z); a0.w = fmaf(w0, x0.w, a0.w);
            a1.x = fmaf(w1, x1.x, a1.x); a1.y = fmaf(w1, x1.y, a1.y);
            a1.z = fmaf(w1, x1.z, a1.z); a1.w = fmaf(w1, x1.w, a1.w);
            a2.x = fmaf(w2, x2.x, a2.x); a2.y = fmaf(w2, x2.y, a2.y);
            a2.z = fmaf(w2, x2.z, a2.z); a2.w = fmaf(w2, x2.w, a2.w);
            a3.x = fmaf(w3, x3.x, a3.x); a3.y = fmaf(w3, x3.y, a3.y);
            a3.z = fmaf(w3, x3.z, a3.z); a3.w = fmaf(w3, x3.w, a3.w);
            a0.x = fmaf(w4, x4.x, a0.x); a0.y = fmaf(w4, x4.y, a0.y);
            a0.z = fmaf(w4, x4.z, a0.z); a0.w = fmaf(w4, x4.w, a0.w);
            a1.x = fmaf(w5, x5.x, a1.x); a1.y = fmaf(w5, x5.y, a1.y);
            a1.z = fmaf(w5, x5.z, a1.z); a1.w = fmaf(w5, x5.w, a1.w);
            a2.x = fmaf(w6, x6.x, a2.x); a2.y = fmaf(w6, x6.y, a2.y);
            a2.z = fmaf(w6, x6.z, a2.z); a2.w = fmaf(w6, x6.w, a2.w);
            a3.x = fmaf(w7, x7.x, a3.x); a3.y = fmaf(w7, x7.y, a3.y);
            a3.z = fmaf(w7, x7.z, a3.z); a3.w = fmaf(w7, x7.w, a3.w);
        }
        // 16-row mid tier: 4 loads in flight
        for (; j + 12 < cnt; j += 16) {
            float4 x0 = *(const float4*)(xb + (long)j * D_DIM);
            float4 x1 = *(const float4*)(xb + (long)(j + 4) * D_DIM);
            float4 x2 = *(const float4*)(xb + (long)(j + 8) * D_DIM);
            float4 x3 = *(const float4*)(xb + (long)(j + 12) * D_DIM);
            float w0 = s_w[j], w1 = s_w[j + 4], w2 = s_w[j + 8], w3 = s_w[j + 12];
            a0.x = fmaf(w0, x0.x, a0.x); a0.y = fmaf(w0, x0.y, a0.y);
            a0.z = fmaf(w0, x0.z, a0.z); a0.w = fmaf(w0, x0.w, a0.w);
            a1.x = fmaf(w1, x1.x, a1.x); a1.y = fmaf(w1, x1.y, a1.y);
            a1.z = fmaf(w1, x1.z, a1.z); a1.w = fmaf(w1, x1.w, a1.w);
            a2.x = fmaf(w2, x2.x, a2.x); a2.y = fmaf(w2, x2.y, a2.y);
            a2.z = fmaf(w2, x2.z, a2.z); a2.w = fmaf(w2, x2.w, a2.w);
            a3.x = fmaf(w3, x3.x, a3.x); a3.y = fmaf(w3, x3.y, a3.y);
            a3.z = fmaf(w3, x3.z, a3.z); a3.w = fmaf(w3, x3.w, a3.w);
        }
        for (; j < cnt; j += 4) {
            float wv = s_w[j];
            float4 xv = *(const float4*)(xb + (long)j * D_DIM);
            a0.x = fmaf(wv, xv.x, a0.x); a0.y = fmaf(wv, xv.y, a0.y);
            a0.z = fmaf(wv, xv.z, a0.z); a0.w = fmaf(wv, xv.w, a0.w);
        }
    }

    a0.x = (a0.x + a1.x) + (a2.x + a3.x);
    a0.y = (a0.y + a1.y) + (a2.y + a3.y);
    a0.z = (a0.z + a1.z) + (a2.z + a3.z);
    a0.w = (a0.w + a1.w) + (a2.w + a3.w);
    s_acc[tid] = a0;
    __syncthreads();

    if (tid < 64) {
        float4 r0 = s_acc[tid],       r1 = s_acc[tid + 64];
        float4 r2 = s_acc[tid + 128], r3 = s_acc[tid + 192];
        float4 o;
        o.x = (r0.x + r1.x) + (r2.x + r3.x);
        o.y = (r0.y + r1.y) + (r2.y + r3.y);
        o.z = (r0.z + r1.z) + (r2.z + r3.z);
        o.w = (r0.w + r1.w) + (r2.w + r3.w);
        *(float4*)(out + (long)g * D_DIM + tid * 4) = o;
    }
}

// ---------------- launch ----------------
extern "C" void kernel_launch(void* const* d_in, const int* in_sizes, int n_in,
                              void* d_out, int out_size) {
    const float* x   = (const float*)d_in[0];
    const int*   seg = (const int*)d_in[1];
    int base = 2;
    if (n_in >= 7 && in_sizes[2] == 1) base = 3;   // skip num_graphs scalar if present
    const float* W1 = (const float*)d_in[base];
    const float* b1 = (const float*)d_in[base + 1];
    const float* W2 = (const float*)d_in[base + 2];
    const float* b2 = (const float*)d_in[base + 3];

    const int N = in_sizes[1];
    const int G = out_size / D_DIM;

    mhap_prep_kernel<<<(NHID * D_DIM / 8 + 255) / 256, 256>>>(W1);     // idx 0
    mhap_dummy_kernel<<<1, 1>>>();                                      // idx 1

    cudaFuncSetAttribute(mhap_score_kernel,
                         cudaFuncAttributeMaxDynamicSharedMemorySize, SMB_TOT);
    mhap_score_kernel<<<(N + TM - 1) / TM, T1, SMB_TOT>>>(x, b1, W2, b2, N);  // idx 2

    mhap_pool_kernel<<<G, 256>>>(x, seg, (float*)d_out, N);             // idx 3
}